// round 7
// baseline (speedup 1.0000x reference)
#include <cuda_runtime.h>

#define CHUNK  128
#define MAXW   79
#define MAXN   (MAXW * CHUNK)   // 10112
#define MAXP   1000
#define SB     4096

typedef unsigned long long u64;

// ---- static device scratch (no allocations allowed) ----
__device__ ulonglong2 g_maskT[(size_t)MAXW * MAXN];  // [word][row] suppression bits
__device__ ulonglong2 g_diag[MAXN];                  // diagonal-block masks
__device__ float4     g_sboxes[MAXN];                // boxes in sorted order
__device__ float      g_sscores[MAXN];               // scores in sorted order
__device__ ulonglong2 g_keep[MAXW];                  // keep bits per 128-chunk
__device__ int        g_prefix[MAXW];                // kept-count prefix per chunk
__device__ int        g_base[SB];                    // bucket base (descending order)
__device__ int        g_members[MAXN];               // indices grouped by bucket

__device__ __forceinline__ int bucket_of(float s) {
    int b = (int)(s * 4096.0f);           // monotone for s >= 0
    return max(0, min(SB - 1, b));
}

// ---------------------------------------------------------------------------
// S1: fused single-block sort front-end: histogram + descending exclusive
// scan + bucket fill. All bucket state lives in shared (no cross-replay
// cleanup needed). 1024 threads.
// ---------------------------------------------------------------------------
__global__ void k_sortA(const float* __restrict__ scores, int N) {
    __shared__ int s_cnt[SB];
    __shared__ int s_base[SB];
    __shared__ int wsum[32];
    int tid = threadIdx.x, lane = tid & 31, wid = tid >> 5;

    for (int b = tid; b < SB; b += 1024) s_cnt[b] = 0;
    __syncthreads();
    for (int i = tid; i < N; i += 1024)
        atomicAdd(&s_cnt[bucket_of(scores[i])], 1);
    __syncthreads();

    int cbase = 0;
    for (int k = 0; k < SB / 1024; k++) {
        int b = SB - 1 - (k * 1024 + tid);   // descending bucket order
        int v = s_cnt[b];
        int x = v;
        #pragma unroll
        for (int o = 1; o < 32; o <<= 1) {
            int y = __shfl_up_sync(~0u, x, o);
            if (lane >= o) x += y;
        }
        if (lane == 31) wsum[wid] = x;
        __syncthreads();
        if (wid == 0) {
            int s = wsum[lane];
            #pragma unroll
            for (int o = 1; o < 32; o <<= 1) {
                int y = __shfl_up_sync(~0u, s, o);
                if (lane >= o) s += y;
            }
            wsum[lane] = s;
        }
        __syncthreads();
        s_base[b] = cbase + (x - v) + (wid ? wsum[wid - 1] : 0);
        cbase += wsum[31];
        __syncthreads();
    }

    // reset counters -> fill cursors; export base for k_place
    for (int b = tid; b < SB; b += 1024) { s_cnt[b] = 0; g_base[b] = s_base[b]; }
    __syncthreads();
    for (int i = tid; i < N; i += 1024) {
        int b = bucket_of(scores[i]);
        int slot = s_base[b] + atomicAdd(&s_cnt[b], 1);
        g_members[slot] = i;
    }
}

// ---------------------------------------------------------------------------
// S2: exact stable rank within bucket + scatter (grid-parallel).
// bucket count recovered from base differences (descending layout).
// ---------------------------------------------------------------------------
__global__ void k_place(const float4* __restrict__ boxes,
                        const float* __restrict__ scores, int N) {
    int i = blockIdx.x * blockDim.x + threadIdx.x;
    if (i >= N) return;
    float si = scores[i];
    int b = bucket_of(si);
    int base = g_base[b];
    int cb   = ((b > 0) ? g_base[b - 1] : N) - base;
    int r = base;
    for (int t = 0; t < cb; t++) {
        int j = g_members[base + t];
        if (j == i) continue;
        float sj = scores[j];
        r += (sj > si) || (sj == si && j < i);
    }
    g_sboxes[r]  = boxes[i];
    g_sscores[r] = si;
}

// ---------------------------------------------------------------------------
// K2: pairwise IoU suppression bitmask, 128x128 tiles, upper triangle.
// suppress <=> IoU > 0.5 <=> 3*inter > areaR + areaC  (division-free).
// Stores TRANSPOSED: g_maskT[word][row] (coalesced across threads).
// ---------------------------------------------------------------------------
__global__ void k_mask(int N, int W) {
    int cb = blockIdx.x, rb = blockIdx.y;
    if (cb < rb) return;
    __shared__ float4 cbox[CHUNK];
    __shared__ float  carea[CHUNK];
    int t  = threadIdx.x;
    int cg = cb * CHUNK + t;
    float4 cv = (cg < N) ? g_sboxes[cg] : make_float4(0.f, 0.f, 0.f, 0.f);
    cbox[t]  = cv;
    carea[t] = (cv.z - cv.x) * (cv.w - cv.y);
    __syncthreads();

    int rg = rb * CHUNK + t;
    if (rg >= N) return;
    float4 r = g_sboxes[rg];
    float ra = (r.z - r.x) * (r.w - r.y);

    u64 m0 = 0, m1 = 0;
    if (cb > rb) {
        #pragma unroll 32
        for (int j = 0; j < 64; j++) {
            float4 c = cbox[j];
            float ix1 = fmaxf(r.x, c.x), iy1 = fmaxf(r.y, c.y);
            float ix2 = fminf(r.z, c.z), iy2 = fminf(r.w, c.w);
            float inter = fmaxf(ix2 - ix1, 0.0f) * fmaxf(iy2 - iy1, 0.0f);
            if (3.0f * inter > ra + carea[j]) m0 |= 1ull << j;
        }
        #pragma unroll 32
        for (int j = 64; j < 128; j++) {
            float4 c = cbox[j];
            float ix1 = fmaxf(r.x, c.x), iy1 = fmaxf(r.y, c.y);
            float ix2 = fminf(r.z, c.z), iy2 = fminf(r.w, c.w);
            float inter = fmaxf(ix2 - ix1, 0.0f) * fmaxf(iy2 - iy1, 0.0f);
            if (3.0f * inter > ra + carea[j]) m1 |= 1ull << (j - 64);
        }
    } else {
        // diagonal tile: only suppress later (lower-score) boxes j > t
        #pragma unroll 32
        for (int j = 0; j < 128; j++) {
            if (j <= t) continue;
            float4 c = cbox[j];
            float ix1 = fmaxf(r.x, c.x), iy1 = fmaxf(r.y, c.y);
            float ix2 = fminf(r.z, c.z), iy2 = fminf(r.w, c.w);
            float inter = fmaxf(ix2 - ix1, 0.0f) * fmaxf(iy2 - iy1, 0.0f);
            if (3.0f * inter > ra + carea[j]) {
                if (j < 64) m0 |= 1ull << j; else m1 |= 1ull << (j - 64);
            }
        }
        g_diag[rg] = make_ulonglong2(m0, m1);
    }
    g_maskT[(size_t)cb * MAXN + rg] = make_ulonglong2(m0, m1);
}

// ---------------------------------------------------------------------------
// K3: pipelined greedy scan. Round c:
//   warp 0:     cooperative gather of critical word c+1 (lanes split kept
//               rows, shfl-OR reduce); lane 0 then runs phase A for chunk
//               c+1 with speculative diag prefetch.
//   tid 32-127: eager per-thread gather into removed[] for words >= c+2.
//   tid 128+:   prefetch diag tile for chunk c+2 (double-buffered).
// One barrier per round. Early termination once MAXP kept.
// ---------------------------------------------------------------------------
__global__ void k_scan(int N, int W) {
    __shared__ ulonglong2 removed[MAXW];
    __shared__ ulonglong2 diagbuf[2][CHUNK];
    __shared__ int klist[2][CHUNK];
    __shared__ int s_nk[2];
    __shared__ int s_stop, s_cstop, s_total;
    int tid = threadIdx.x, lane = tid & 31;

    for (int w = tid; w < W; w += 256) removed[w] = make_ulonglong2(0ull, 0ull);
    if (tid < CHUNK) {
        diagbuf[0][tid] = (tid < N) ? g_diag[tid] : make_ulonglong2(0ull, 0ull);
    } else {
        int g = CHUNK + (tid - CHUNK);
        diagbuf[1][tid - CHUNK] = (W > 1 && g < N) ? g_diag[g] : make_ulonglong2(0ull, 0ull);
    }
    if (tid == 0) { s_stop = 0; s_cstop = W; s_total = 0; }
    __syncthreads();

    // phase A for chunk 0
    if (tid == 0) {
        const ulonglong2* d = diagbuf[0];
        int valid = min(N, CHUNK);
        u64 p0 = (valid >= 64) ? ~0ull : ((1ull << valid) - 1ull);
        int v2 = valid - 64;
        u64 p1 = (v2 >= 64) ? ~0ull : ((v2 <= 0) ? 0ull : ((1ull << v2) - 1ull));
        u64 k0 = 0ull, k1 = 0ull;
        int n = 0;
        int i = p0 ? (__ffsll((long long)p0) - 1)
                   : (p1 ? 64 + __ffsll((long long)p1) - 1 : -1);
        ulonglong2 dd = (i >= 0) ? d[i] : make_ulonglong2(0ull, 0ull);
        while (i >= 0) {
            if (i < 64) { k0 |= 1ull << i; p0 &= ~(1ull << i); }
            else        { k1 |= 1ull << (i - 64); p1 &= ~(1ull << (i - 64)); }
            klist[0][n++] = i;
            int j = p0 ? (__ffsll((long long)p0) - 1)
                       : (p1 ? 64 + __ffsll((long long)p1) - 1 : -1);
            ulonglong2 ddj = (j >= 0) ? d[j] : make_ulonglong2(0ull, 0ull);
            p0 &= ~dd.x; p1 &= ~dd.y;
            int i2 = p0 ? (__ffsll((long long)p0) - 1)
                        : (p1 ? 64 + __ffsll((long long)p1) - 1 : -1);
            if (i2 == j) { i = j; dd = ddj; }
            else { i = i2; if (i2 >= 0) dd = d[i2]; }
        }
        g_keep[0] = make_ulonglong2(k0, k1);
        g_prefix[0] = 0;
        int tot = __popcll(k0) + __popcll(k1);
        s_total = tot;
        s_nk[0] = n;
        if (tot >= MAXP) { s_stop = 1; s_cstop = 1; }
    }
    __syncthreads();

    for (int c = 0; c + 1 < W; c++) {
        if (s_stop) break;
        int pb = c & 1;
        int nk = s_nk[pb];
        const int* kl = klist[pb];
        size_t cb128 = (size_t)c * CHUNK;

        if (tid < 32) {
            // cooperative gather of critical word c+1
            int wc = c + 1;
            const ulonglong2* mp = g_maskT + (size_t)wc * MAXN + cb128;
            u64 ax = 0ull, ay = 0ull;
            for (int t = lane; t < nk; t += 32) {
                ulonglong2 v = mp[kl[t]];
                ax |= v.x; ay |= v.y;
            }
            #pragma unroll
            for (int o = 16; o; o >>= 1) {
                ax |= __shfl_xor_sync(~0u, ax, o);
                ay |= __shfl_xor_sync(~0u, ay, o);
            }
            if (lane == 0) {
                ulonglong2 rm = removed[wc];
                u64 r0 = rm.x | ax, r1 = rm.y | ay;
                int cc = wc;
                const ulonglong2* d = diagbuf[cc & 1];
                int valid = N - cc * CHUNK;
                u64 v0 = (valid >= 64) ? ~0ull : ((valid <= 0) ? 0ull : ((1ull << valid) - 1ull));
                int vv = valid - 64;
                u64 v1 = (vv >= 64) ? ~0ull : ((vv <= 0) ? 0ull : ((1ull << vv) - 1ull));
                u64 p0 = ~r0 & v0, p1 = ~r1 & v1;
                u64 k0 = 0ull, k1 = 0ull;
                int n = 0;
                int* klo = klist[cc & 1];
                int i = p0 ? (__ffsll((long long)p0) - 1)
                           : (p1 ? 64 + __ffsll((long long)p1) - 1 : -1);
                ulonglong2 dd = (i >= 0) ? d[i] : make_ulonglong2(0ull, 0ull);
                while (i >= 0) {
                    if (i < 64) { k0 |= 1ull << i; p0 &= ~(1ull << i); }
                    else        { k1 |= 1ull << (i - 64); p1 &= ~(1ull << (i - 64)); }
                    klo[n++] = i;
                    int j = p0 ? (__ffsll((long long)p0) - 1)
                               : (p1 ? 64 + __ffsll((long long)p1) - 1 : -1);
                    ulonglong2 ddj = (j >= 0) ? d[j] : make_ulonglong2(0ull, 0ull);
                    p0 &= ~dd.x; p1 &= ~dd.y;
                    int i2 = p0 ? (__ffsll((long long)p0) - 1)
                                : (p1 ? 64 + __ffsll((long long)p1) - 1 : -1);
                    if (i2 == j) { i = j; dd = ddj; }
                    else { i = i2; if (i2 >= 0) dd = d[i2]; }
                }
                g_keep[cc] = make_ulonglong2(k0, k1);
                g_prefix[cc] = s_total;
                int tot = s_total + __popcll(k0) + __popcll(k1);
                s_total = tot;
                s_nk[cc & 1] = n;
                if (tot >= MAXP) { s_stop = 1; s_cstop = cc + 1; }
            }
        } else if (tid < 128) {
            // eager scatter for future words (off critical path)
            int w = c + 2 + (tid - 32);
            if (w < W) {
                ulonglong2 acc = removed[w];
                const ulonglong2* mp = g_maskT + (size_t)w * MAXN + cb128;
                for (int t = 0; t < nk; t += 8) {
                    u64 ax = 0ull, ay = 0ull;
                    #pragma unroll
                    for (int u = 0; u < 8; u++) {
                        if (t + u < nk) {
                            ulonglong2 v = mp[kl[t + u]];
                            ax |= v.x; ay |= v.y;
                        }
                    }
                    acc.x |= ax; acc.y |= ay;
                }
                removed[w] = acc;
            }
        } else {
            // prefetch diag tile for chunk c+2
            if (c + 2 < W) {
                int g = (c + 2) * CHUNK + (tid - 128);
                diagbuf[c & 1][tid - 128] =
                    (g < N) ? g_diag[g] : make_ulonglong2(0ull, 0ull);
            }
        }
        __syncthreads();
    }

    int cstop = s_cstop;
    for (int c2 = cstop + tid; c2 < W; c2 += 256)
        g_keep[c2] = make_ulonglong2(0ull, 0ull);
}

// ---------------------------------------------------------------------------
// K4: apply MAX_PROPOSALS cutoff and emit outputs:
//   out[0 : 4N) boxes | out[4N : 5N) scores | out[5N : 6N) keep as 0/1
// ---------------------------------------------------------------------------
__global__ void k_out(float* __restrict__ out, int N) {
    int p = blockIdx.x * blockDim.x + threadIdx.x;
    if (p >= N) return;
    int c = p >> 7, i = p & 127;
    ulonglong2 kw = g_keep[c];
    bool kept;
    int below;
    if (i < 64) {
        kept  = (kw.x >> i) & 1ull;
        below = __popcll(kw.x & ((1ull << i) - 1ull));
    } else {
        int ii = i - 64;
        kept  = (kw.y >> ii) & 1ull;
        below = __popcll(kw.x) + __popcll(kw.y & ((1ull << ii) - 1ull));
    }
    int r = g_prefix[c] + below;
    bool fin = kept && (r < MAXP);

    float4 b = fin ? g_sboxes[p] : make_float4(0.f, 0.f, 0.f, 0.f);
    ((float4*)out)[p] = b;
    out[4 * N + p] = fin ? g_sscores[p] : 0.0f;
    out[5 * N + p] = fin ? 1.0f : 0.0f;
}

// ---------------------------------------------------------------------------
extern "C" void kernel_launch(void* const* d_in, const int* in_sizes, int n_in,
                              void* d_out, int out_size) {
    const float4* boxes  = (const float4*)d_in[0];
    const float*  scores = (const float*)d_in[1];
    int N = in_sizes[1];
    int W = (N + CHUNK - 1) / CHUNK;

    k_sortA<<<1, 1024>>>(scores, N);
    k_place<<<(N + 255) / 256, 256>>>(boxes, scores, N);

    dim3 g2(W, W);
    k_mask<<<g2, CHUNK>>>(N, W);

    k_scan<<<1, 256>>>(N, W);

    k_out<<<(N + 255) / 256, 256>>>((float*)d_out, N);
}

// round 8
// speedup vs baseline: 1.0790x; 1.0790x over previous
#include <cuda_runtime.h>

#define CHUNK  128
#define MAXW   79
#define MAXN   (MAXW * CHUNK)   // 10112
#define MAXP   1000
#define SB     4096
#define KCAP   1280              // max kept rows tracked (999 + 128 < 1280)

typedef unsigned long long u64;

// ---- static device scratch (no allocations allowed) ----
__device__ ulonglong2 g_maskT[(size_t)MAXW * MAXN];  // [word][row] suppression bits
__device__ ulonglong2 g_diag[MAXN];                  // diagonal-block masks
__device__ float4     g_sboxes[MAXN];                // boxes in sorted order
__device__ float      g_sscores[MAXN];               // scores in sorted order
__device__ ulonglong2 g_keep[MAXW];                  // keep bits per 128-chunk
__device__ int        g_prefix[MAXW];                // kept-count prefix per chunk
__device__ int        g_base[SB];                    // bucket base (descending order)
__device__ int        g_members[MAXN];               // indices grouped by bucket

__device__ __forceinline__ int bucket_of(float s) {
    int b = (int)(s * 4096.0f);           // monotone for s >= 0
    return max(0, min(SB - 1, b));
}

// ---------------------------------------------------------------------------
// S1: fused single-block sort front-end: histogram + descending exclusive
// scan + bucket fill. All bucket state in shared (no cross-replay cleanup).
// ---------------------------------------------------------------------------
__global__ void k_sortA(const float* __restrict__ scores, int N) {
    __shared__ int s_cnt[SB];
    __shared__ int s_base[SB];
    __shared__ int wsum[32];
    int tid = threadIdx.x, lane = tid & 31, wid = tid >> 5;

    for (int b = tid; b < SB; b += 1024) s_cnt[b] = 0;
    __syncthreads();
    for (int i = tid; i < N; i += 1024)
        atomicAdd(&s_cnt[bucket_of(scores[i])], 1);
    __syncthreads();

    int cbase = 0;
    for (int k = 0; k < SB / 1024; k++) {
        int b = SB - 1 - (k * 1024 + tid);   // descending bucket order
        int v = s_cnt[b];
        int x = v;
        #pragma unroll
        for (int o = 1; o < 32; o <<= 1) {
            int y = __shfl_up_sync(~0u, x, o);
            if (lane >= o) x += y;
        }
        if (lane == 31) wsum[wid] = x;
        __syncthreads();
        if (wid == 0) {
            int s = wsum[lane];
            #pragma unroll
            for (int o = 1; o < 32; o <<= 1) {
                int y = __shfl_up_sync(~0u, s, o);
                if (lane >= o) s += y;
            }
            wsum[lane] = s;
        }
        __syncthreads();
        s_base[b] = cbase + (x - v) + (wid ? wsum[wid - 1] : 0);
        cbase += wsum[31];
        __syncthreads();
    }

    for (int b = tid; b < SB; b += 1024) { s_cnt[b] = 0; g_base[b] = s_base[b]; }
    __syncthreads();
    for (int i = tid; i < N; i += 1024) {
        int b = bucket_of(scores[i]);
        int slot = s_base[b] + atomicAdd(&s_cnt[b], 1);
        g_members[slot] = i;
    }
}

// ---------------------------------------------------------------------------
// S2: exact stable rank within bucket + scatter (grid-parallel).
// ---------------------------------------------------------------------------
__global__ void k_place(const float4* __restrict__ boxes,
                        const float* __restrict__ scores, int N) {
    int i = blockIdx.x * blockDim.x + threadIdx.x;
    if (i >= N) return;
    float si = scores[i];
    int b = bucket_of(si);
    int base = g_base[b];
    int cb   = ((b > 0) ? g_base[b - 1] : N) - base;
    int r = base;
    for (int t = 0; t < cb; t++) {
        int j = g_members[base + t];
        if (j == i) continue;
        float sj = scores[j];
        r += (sj > si) || (sj == si && j < i);
    }
    g_sboxes[r]  = boxes[i];
    g_sscores[r] = si;
}

// ---------------------------------------------------------------------------
// K2: pairwise IoU suppression bitmask, 128x128 tiles, upper triangle.
// suppress <=> IoU > 0.5 <=> 3*inter > areaR + areaC  (division-free).
// Stores TRANSPOSED: g_maskT[word][row].
// ---------------------------------------------------------------------------
__global__ void k_mask(int N, int W) {
    int cb = blockIdx.x, rb = blockIdx.y;
    if (cb < rb) return;
    __shared__ float4 cbox[CHUNK];
    __shared__ float  carea[CHUNK];
    int t  = threadIdx.x;
    int cg = cb * CHUNK + t;
    float4 cv = (cg < N) ? g_sboxes[cg] : make_float4(0.f, 0.f, 0.f, 0.f);
    cbox[t]  = cv;
    carea[t] = (cv.z - cv.x) * (cv.w - cv.y);
    __syncthreads();

    int rg = rb * CHUNK + t;
    if (rg >= N) return;
    float4 r = g_sboxes[rg];
    float ra = (r.z - r.x) * (r.w - r.y);

    u64 m0 = 0, m1 = 0;
    if (cb > rb) {
        #pragma unroll 32
        for (int j = 0; j < 64; j++) {
            float4 c = cbox[j];
            float ix1 = fmaxf(r.x, c.x), iy1 = fmaxf(r.y, c.y);
            float ix2 = fminf(r.z, c.z), iy2 = fminf(r.w, c.w);
            float inter = fmaxf(ix2 - ix1, 0.0f) * fmaxf(iy2 - iy1, 0.0f);
            if (3.0f * inter > ra + carea[j]) m0 |= 1ull << j;
        }
        #pragma unroll 32
        for (int j = 64; j < 128; j++) {
            float4 c = cbox[j];
            float ix1 = fmaxf(r.x, c.x), iy1 = fmaxf(r.y, c.y);
            float ix2 = fminf(r.z, c.z), iy2 = fminf(r.w, c.w);
            float inter = fmaxf(ix2 - ix1, 0.0f) * fmaxf(iy2 - iy1, 0.0f);
            if (3.0f * inter > ra + carea[j]) m1 |= 1ull << (j - 64);
        }
    } else {
        #pragma unroll 32
        for (int j = 0; j < 128; j++) {
            if (j <= t) continue;  // diagonal: only suppress later boxes
            float4 c = cbox[j];
            float ix1 = fmaxf(r.x, c.x), iy1 = fmaxf(r.y, c.y);
            float ix2 = fminf(r.z, c.z), iy2 = fminf(r.w, c.w);
            float inter = fmaxf(ix2 - ix1, 0.0f) * fmaxf(iy2 - iy1, 0.0f);
            if (3.0f * inter > ra + carea[j]) {
                if (j < 64) m0 |= 1ull << j; else m1 |= 1ull << (j - 64);
            }
        }
        g_diag[rg] = make_ulonglong2(m0, m1);
    }
    g_maskT[(size_t)cb * MAXN + rg] = make_ulonglong2(m0, m1);
}

// ---------------------------------------------------------------------------
// phase A: serial greedy within one 128-chunk with speculative diag prefetch.
// Appends kept local indices to klist (as GLOBAL row ids), returns count.
// ---------------------------------------------------------------------------
__device__ __forceinline__ int phaseA(const ulonglong2* d, u64 r0, u64 r1,
                                      int valid, int gbase,
                                      int* klist, u64& k0o, u64& k1o) {
    u64 v0 = (valid >= 64) ? ~0ull : ((valid <= 0) ? 0ull : ((1ull << valid) - 1ull));
    int vv = valid - 64;
    u64 v1 = (vv >= 64) ? ~0ull : ((vv <= 0) ? 0ull : ((1ull << vv) - 1ull));
    u64 p0 = ~r0 & v0, p1 = ~r1 & v1;
    u64 k0 = 0ull, k1 = 0ull;
    int n = 0;
    int i = p0 ? (__ffsll((long long)p0) - 1)
               : (p1 ? 64 + __ffsll((long long)p1) - 1 : -1);
    ulonglong2 dd = (i >= 0) ? d[i] : make_ulonglong2(0ull, 0ull);
    while (i >= 0) {
        if (i < 64) { k0 |= 1ull << i; p0 &= ~(1ull << i); }
        else        { k1 |= 1ull << (i - 64); p1 &= ~(1ull << (i - 64)); }
        klist[n++] = gbase + i;
        int j = p0 ? (__ffsll((long long)p0) - 1)
                   : (p1 ? 64 + __ffsll((long long)p1) - 1 : -1);
        ulonglong2 ddj = (j >= 0) ? d[j] : make_ulonglong2(0ull, 0ull);
        p0 &= ~dd.x; p1 &= ~dd.y;
        int i2 = p0 ? (__ffsll((long long)p0) - 1)
                    : (p1 ? 64 + __ffsll((long long)p1) - 1 : -1);
        if (i2 == j) { i = j; dd = ddj; }
        else { i = i2; if (i2 >= 0) dd = d[i2]; }
    }
    k0o = k0; k1o = k1;
    return n;
}

// ---------------------------------------------------------------------------
// K3: lazy greedy scan. Round c (process chunk wc=c+1):
//   phase 1: ALL 256 threads gather OR over the global kept list of
//            maskT[wc][kept_row]  (<=5 independent loads/thread, 8 warps).
//   phase 2: thread 0 reduces partials + runs phase A, appending new kept
//            rows; threads 128..255 concurrently prefetch diag tile c+2.
// Early termination once total kept >= MAXP.
// ---------------------------------------------------------------------------
__global__ void k_scan(int N, int W) {
    __shared__ ulonglong2 diagbuf[2][CHUNK];
    __shared__ ulonglong2 s_part[8];
    __shared__ int s_klist[KCAP];
    __shared__ int s_K, s_stop, s_cstop, s_total;
    int tid = threadIdx.x, lane = tid & 31, wid = tid >> 5;

    if (tid < CHUNK) {
        diagbuf[0][tid] = (tid < N) ? g_diag[tid] : make_ulonglong2(0ull, 0ull);
    } else {
        int g = CHUNK + (tid - CHUNK);
        diagbuf[1][tid - CHUNK] = (W > 1 && g < N) ? g_diag[g] : make_ulonglong2(0ull, 0ull);
    }
    if (tid == 0) { s_stop = 0; s_cstop = W; s_total = 0; s_K = 0; }
    __syncthreads();

    // chunk 0
    if (tid == 0) {
        u64 k0, k1;
        int n = phaseA(diagbuf[0], 0ull, 0ull, min(N, CHUNK), 0, s_klist, k0, k1);
        g_keep[0] = make_ulonglong2(k0, k1);
        g_prefix[0] = 0;
        int tot = __popcll(k0) + __popcll(k1);
        s_total = tot; s_K = n;
        if (tot >= MAXP) { s_stop = 1; s_cstop = 1; }
    }
    __syncthreads();

    for (int c = 0; c + 1 < W; c++) {
        if (s_stop) break;
        int wc = c + 1;
        int K = s_K;

        // phase 1: cooperative gather of chunk wc's suppression word
        const ulonglong2* mp = g_maskT + (size_t)wc * MAXN;
        u64 ax = 0ull, ay = 0ull;
        for (int t = tid; t < K; t += 256) {
            ulonglong2 v = mp[s_klist[t]];
            ax |= v.x; ay |= v.y;
        }
        #pragma unroll
        for (int o = 16; o; o >>= 1) {
            ax |= __shfl_xor_sync(~0u, ax, o);
            ay |= __shfl_xor_sync(~0u, ay, o);
        }
        if (lane == 0) s_part[wid] = make_ulonglong2(ax, ay);
        __syncthreads();

        // phase 2: thread 0 reduce + phase A; tid>=128 prefetch diag c+2
        if (tid == 0) {
            u64 r0 = 0ull, r1 = 0ull;
            #pragma unroll
            for (int p = 0; p < 8; p++) {
                ulonglong2 v = s_part[p];
                r0 |= v.x; r1 |= v.y;
            }
            u64 k0, k1;
            int n = phaseA(diagbuf[wc & 1], r0, r1, N - wc * CHUNK,
                           wc * CHUNK, s_klist + K, k0, k1);
            g_keep[wc] = make_ulonglong2(k0, k1);
            g_prefix[wc] = s_total;
            int tot = s_total + __popcll(k0) + __popcll(k1);
            s_total = tot; s_K = K + n;
            if (tot >= MAXP) { s_stop = 1; s_cstop = wc + 1; }
        } else if (tid >= 128 && c + 2 < W) {
            int g = (c + 2) * CHUNK + (tid - 128);
            diagbuf[c & 1][tid - 128] =
                (g < N) ? g_diag[g] : make_ulonglong2(0ull, 0ull);
        }
        __syncthreads();
    }

    int cstop = s_cstop;
    for (int c2 = cstop + tid; c2 < W; c2 += 256)
        g_keep[c2] = make_ulonglong2(0ull, 0ull);
}

// ---------------------------------------------------------------------------
// K4: apply MAX_PROPOSALS cutoff and emit outputs:
//   out[0 : 4N) boxes | out[4N : 5N) scores | out[5N : 6N) keep as 0/1
// ---------------------------------------------------------------------------
__global__ void k_out(float* __restrict__ out, int N) {
    int p = blockIdx.x * blockDim.x + threadIdx.x;
    if (p >= N) return;
    int c = p >> 7, i = p & 127;
    ulonglong2 kw = g_keep[c];
    bool kept;
    int below;
    if (i < 64) {
        kept  = (kw.x >> i) & 1ull;
        below = __popcll(kw.x & ((1ull << i) - 1ull));
    } else {
        int ii = i - 64;
        kept  = (kw.y >> ii) & 1ull;
        below = __popcll(kw.x) + __popcll(kw.y & ((1ull << ii) - 1ull));
    }
    int r = g_prefix[c] + below;
    bool fin = kept && (r < MAXP);

    float4 b = fin ? g_sboxes[p] : make_float4(0.f, 0.f, 0.f, 0.f);
    ((float4*)out)[p] = b;
    out[4 * N + p] = fin ? g_sscores[p] : 0.0f;
    out[5 * N + p] = fin ? 1.0f : 0.0f;
}

// ---------------------------------------------------------------------------
extern "C" void kernel_launch(void* const* d_in, const int* in_sizes, int n_in,
                              void* d_out, int out_size) {
    const float4* boxes  = (const float4*)d_in[0];
    const float*  scores = (const float*)d_in[1];
    int N = in_sizes[1];
    int W = (N + CHUNK - 1) / CHUNK;

    k_sortA<<<1, 1024>>>(scores, N);
    k_place<<<(N + 255) / 256, 256>>>(boxes, scores, N);

    dim3 g2(W, W);
    k_mask<<<g2, CHUNK>>>(N, W);

    k_scan<<<1, 256>>>(N, W);

    k_out<<<(N + 255) / 256, 256>>>((float*)d_out, N);
}